// round 2
// baseline (speedup 1.0000x reference)
#include <cuda_runtime.h>
#include <cuda_bf16.h>
#include <cstdint>

// Problem constants
#define LNUM 8
#define D 1024
#define H 16
#define CH 64          // head dim
#define MSZ 4096
#define V 64
#define TMAX 2048
#define BB 4
#define TT 2048
#define ROWS (BB*TT)   // 8192
#define EPS 1e-5f

// ---------------- scratch (device globals; no allocations allowed) ----------
__device__ float g_x[ROWS * D];
__device__ float g_h[ROWS * D];
__device__ float g_ln[ROWS * D];
__device__ float g_qkv[ROWS * 3 * D];
__device__ float g_attn[ROWS * D];
__device__ float g_mid[ROWS * MSZ];
__device__ float g_mlp[ROWS * D];

// ---------------- embedding: x = toks @ Wtok^T + Wpos^T[:T] -----------------
__global__ __launch_bounds__(256) void embed_kernel(
    const float* __restrict__ toks, const float* __restrict__ Wtok,
    const float* __restrict__ Wpos, float* __restrict__ x)
{
    int bt = blockIdx.x;              // 0..ROWS-1
    int t = bt % TT;
    __shared__ float tk[V];
    if (threadIdx.x < V) tk[threadIdx.x] = toks[(size_t)bt * V + threadIdx.x];
    __syncthreads();
    for (int d = threadIdx.x; d < D; d += 256) {
        float s = Wpos[(size_t)d * TMAX + t];
        const float* wr = Wtok + (size_t)d * V;
        #pragma unroll 16
        for (int v = 0; v < V; v++) s += tk[v] * wr[v];
        x[(size_t)bt * D + d] = s;
    }
}

// ---------------- layernorm over D=1024, one block per row ------------------
__global__ __launch_bounds__(256) void ln_kernel(
    const float* __restrict__ x, const float* __restrict__ g,
    const float* __restrict__ be, float* __restrict__ out)
{
    int row = blockIdx.x;
    const float* xr = x + (size_t)row * D;
    int tid = threadIdx.x;
    float v[4];
    float s = 0.f;
    #pragma unroll
    for (int i = 0; i < 4; i++) { v[i] = xr[tid + i * 256]; s += v[i]; }

    __shared__ float red[8];
    #pragma unroll
    for (int o = 16; o; o >>= 1) s += __shfl_xor_sync(0xffffffffu, s, o);
    if ((tid & 31) == 0) red[tid >> 5] = s;
    __syncthreads();
    if (tid < 32) {
        float t2 = (tid < 8) ? red[tid] : 0.f;
        #pragma unroll
        for (int o = 4; o; o >>= 1) t2 += __shfl_xor_sync(0xffffffffu, t2, o);
        if (tid == 0) red[0] = t2;
    }
    __syncthreads();
    float mean = red[0] * (1.f / D);
    __syncthreads();

    float s2 = 0.f;
    #pragma unroll
    for (int i = 0; i < 4; i++) { float d0 = v[i] - mean; s2 += d0 * d0; }
    #pragma unroll
    for (int o = 16; o; o >>= 1) s2 += __shfl_xor_sync(0xffffffffu, s2, o);
    if ((tid & 31) == 0) red[tid >> 5] = s2;
    __syncthreads();
    if (tid < 32) {
        float t2 = (tid < 8) ? red[tid] : 0.f;
        #pragma unroll
        for (int o = 4; o; o >>= 1) t2 += __shfl_xor_sync(0xffffffffu, t2, o);
        if (tid == 0) red[0] = t2;
    }
    __syncthreads();
    float var = red[0] * (1.f / D);
    float rstd = rsqrtf(var + EPS);

    float* orow = out + (size_t)row * D;
    #pragma unroll
    for (int i = 0; i < 4; i++) {
        int d0 = tid + i * 256;
        orow[d0] = (v[i] - mean) * rstd * g[d0] + be[d0];
    }
}

// ---------------- NT GEMM: C[M,N] = A[M,K] * B[N,K]^T + bias, opt relu ------
#define BM 128
#define BN 128
#define BK 16
#define TM 8
#define TN 8

__global__ __launch_bounds__(256) void gemm_nt_kernel(
    const float* __restrict__ A, const float* __restrict__ B,
    const float* __restrict__ bias, float* __restrict__ C,
    int Mrows, int N, int K, int relu)
{
    __shared__ float As[BK][BM];
    __shared__ float Bs[BK][BN];
    int tid = threadIdx.x;
    int tx = tid & 15, ty = tid >> 4;
    int rowA0 = blockIdx.y * BM;
    int colB0 = blockIdx.x * BN;

    float acc[TM][TN];
    #pragma unroll
    for (int i = 0; i < TM; i++)
        #pragma unroll
        for (int j = 0; j < TN; j++) acc[i][j] = 0.f;

    for (int k0 = 0; k0 < K; k0 += BK) {
        #pragma unroll
        for (int i = 0; i < 8; i++) {
            int li = tid + i * 256;
            int r = li >> 4, c = li & 15;
            As[c][r] = A[(size_t)(rowA0 + r) * K + k0 + c];
            int bn = colB0 + r;
            Bs[c][r] = (bn < N) ? B[(size_t)bn * K + k0 + c] : 0.f;
        }
        __syncthreads();
        #pragma unroll
        for (int k = 0; k < BK; k++) {
            float a[TM], b[TN];
            const float4* A4 = reinterpret_cast<const float4*>(&As[k][ty * TM]);
            const float4* B4 = reinterpret_cast<const float4*>(&Bs[k][tx * TN]);
            float4 a0 = A4[0], a1 = A4[1];
            float4 b0 = B4[0], b1 = B4[1];
            a[0]=a0.x; a[1]=a0.y; a[2]=a0.z; a[3]=a0.w;
            a[4]=a1.x; a[5]=a1.y; a[6]=a1.z; a[7]=a1.w;
            b[0]=b0.x; b[1]=b0.y; b[2]=b0.z; b[3]=b0.w;
            b[4]=b1.x; b[5]=b1.y; b[6]=b1.z; b[7]=b1.w;
            #pragma unroll
            for (int i = 0; i < TM; i++)
                #pragma unroll
                for (int j = 0; j < TN; j++)
                    acc[i][j] = fmaf(a[i], b[j], acc[i][j]);
        }
        __syncthreads();
    }

    #pragma unroll
    for (int i = 0; i < TM; i++) {
        int row = rowA0 + ty * TM + i;
        #pragma unroll
        for (int j = 0; j < TN; j++) {
            int col = colB0 + tx * TN + j;
            if (col < N) {
                float vv = acc[i][j] + (bias ? bias[col] : 0.f);
                if (relu) vv = fmaxf(vv, 0.f);
                C[(size_t)row * N + col] = vv;
            }
        }
    }
}

// ---------------- causal attention from interleaved qkv ---------------------
// qkv row layout per (b,t): [H][3*CH] = q(64) k(64) v(64) per head.
// out[b,t, h*CH + c]. One thread per query row, 128 queries per block.
#define TS 32
__global__ __launch_bounds__(128) void attn_kernel(
    const float* __restrict__ qkv, float* __restrict__ out)
{
    int qt0 = blockIdx.x * 128;
    int h = blockIdx.y, b = blockIdx.z;
    int tid = threadIdx.x;
    int t = qt0 + tid;

    __shared__ float Ks[TS][CH];
    __shared__ float Vs[TS][CH];
    __shared__ float Ss[128][TS + 1];

    const size_t rstride = 3 * D;
    const float* base = qkv + (size_t)b * TT * rstride + (size_t)h * 3 * CH;

    float q[CH];
    const float* qr = base + (size_t)t * rstride;
    #pragma unroll
    for (int c = 0; c < CH; c++) q[c] = qr[c] * 0.125f;  // 1/sqrt(64)

    float acc[CH];
    #pragma unroll
    for (int c = 0; c < CH; c++) acc[c] = 0.f;
    float m = -1e30f, l = 0.f;

    int smax = qt0 + 127;
    for (int s0 = 0; s0 <= smax; s0 += TS) {
        for (int i = tid; i < TS * CH; i += 128) {
            int s = i >> 6, c = i & 63;
            const float* kr = base + (size_t)(s0 + s) * rstride;
            Ks[s][c] = kr[CH + c];
            Vs[s][c] = kr[2 * CH + c];
        }
        __syncthreads();

        float mt = -1e30f;
        for (int s = 0; s < TS; s++) {
            float sc = 0.f;
            #pragma unroll
            for (int c = 0; c < CH; c++) sc = fmaf(q[c], Ks[s][c], sc);
            if (s0 + s > t) sc = -1e30f;
            Ss[tid][s] = sc;
            mt = fmaxf(mt, sc);
        }
        float mn = fmaxf(m, mt);
        float corr = __expf(m - mn);
        l *= corr;
        #pragma unroll
        for (int c = 0; c < CH; c++) acc[c] *= corr;
        for (int s = 0; s < TS; s++) {
            float p = __expf(Ss[tid][s] - mn);
            l += p;
            #pragma unroll
            for (int c = 0; c < CH; c++) acc[c] = fmaf(p, Vs[s][c], acc[c]);
        }
        m = mn;
        __syncthreads();
    }

    float inv = 1.f / l;
    float* o = out + ((size_t)b * TT + t) * D + h * CH;
    #pragma unroll
    for (int c = 0; c < CH; c++) o[c] = acc[c] * inv;
}

// ---------------- elementwise residual adds ---------------------------------
__global__ __launch_bounds__(256) void add2_kernel(
    const float* __restrict__ a, const float* __restrict__ b, float* __restrict__ o, int n4)
{
    int i = blockIdx.x * blockDim.x + threadIdx.x;
    if (i < n4) {
        float4 x = reinterpret_cast<const float4*>(a)[i];
        float4 y = reinterpret_cast<const float4*>(b)[i];
        x.x += y.x; x.y += y.y; x.z += y.z; x.w += y.w;
        reinterpret_cast<float4*>(o)[i] = x;
    }
}

__global__ __launch_bounds__(256) void add3_kernel(
    float* __restrict__ x, const float* __restrict__ h, const float* __restrict__ mlp, int n4)
{
    int i = blockIdx.x * blockDim.x + threadIdx.x;
    if (i < n4) {
        float4 a = reinterpret_cast<float4*>(x)[i];
        float4 b = reinterpret_cast<const float4*>(h)[i];
        float4 c = reinterpret_cast<const float4*>(mlp)[i];
        a.x += b.x + c.x; a.y += b.y + c.y; a.z += b.z + c.z; a.w += b.w + c.w;
        reinterpret_cast<float4*>(x)[i] = a;
    }
}

// ---------------- driver -----------------------------------------------------
extern "C" void kernel_launch(void* const* d_in, const int* in_sizes, int n_in,
                              void* d_out, int out_size)
{
    const float* toks  = (const float*)d_in[0];
    const float* W_tok = (const float*)d_in[1];
    const float* W_pos = (const float*)d_in[2];
    const float* Wqkv  = (const float*)d_in[3];
    const float* g1    = (const float*)d_in[4];
    const float* be1   = (const float*)d_in[5];
    const float* W1    = (const float*)d_in[6];
    const float* bm1   = (const float*)d_in[7];
    const float* W2    = (const float*)d_in[8];
    const float* bm2   = (const float*)d_in[9];
    const float* g2    = (const float*)d_in[10];
    const float* be2   = (const float*)d_in[11];
    const float* gf    = (const float*)d_in[12];
    const float* bf    = (const float*)d_in[13];
    const float* Wun   = (const float*)d_in[14];
    const float* bun   = (const float*)d_in[15];
    float* out = (float*)d_out;

    float *px, *ph, *pln, *pqkv, *pattn, *pmid, *pmlp;
    cudaGetSymbolAddress((void**)&px,   g_x);
    cudaGetSymbolAddress((void**)&ph,   g_h);
    cudaGetSymbolAddress((void**)&pln,  g_ln);
    cudaGetSymbolAddress((void**)&pqkv, g_qkv);
    cudaGetSymbolAddress((void**)&pattn,g_attn);
    cudaGetSymbolAddress((void**)&pmid, g_mid);
    cudaGetSymbolAddress((void**)&pmlp, g_mlp);

    const int n4 = ROWS * D / 4;
    const int addGrid = (n4 + 255) / 256;

    // embedding
    embed_kernel<<<ROWS, 256>>>(toks, W_tok, W_pos, px);

    for (int l = 0; l < LNUM; l++) {
        const float* wqkv = Wqkv + (size_t)l * 3 * D * D;
        const float* w1   = W1   + (size_t)l * MSZ * D;
        const float* w2   = W2   + (size_t)l * D * MSZ;

        // ln1 -> qkv gemm -> attention
        ln_kernel<<<ROWS, 256>>>(px, g1 + l * D, be1 + l * D, pln);
        {
            dim3 grid((3 * D + BN - 1) / BN, ROWS / BM);
            gemm_nt_kernel<<<grid, 256>>>(pln, wqkv, nullptr, pqkv, ROWS, 3 * D, D, 0);
        }
        {
            dim3 grid(TT / 128, H, BB);
            attn_kernel<<<grid, 128>>>(pqkv, pattn);
        }
        // h = x + attn
        add2_kernel<<<addGrid, 256>>>(px, pattn, ph, n4);

        // ln2 -> mlp
        ln_kernel<<<ROWS, 256>>>(ph, g2 + l * D, be2 + l * D, pln);
        {
            dim3 grid((MSZ + BN - 1) / BN, ROWS / BM);
            gemm_nt_kernel<<<grid, 256>>>(pln, w1, bm1 + (size_t)l * MSZ, pmid, ROWS, MSZ, D, 1);
        }
        {
            dim3 grid((D + BN - 1) / BN, ROWS / BM);
            gemm_nt_kernel<<<grid, 256>>>(pmid, w2, bm2 + (size_t)l * D, pmlp, ROWS, D, MSZ, 0);
        }
        // x = x + h + mlp   (reference: x = x + (h_after_attn + mlp_out))
        add3_kernel<<<addGrid, 256>>>(px, ph, pmlp, n4);
    }

    // final layernorm + unembed
    ln_kernel<<<ROWS, 256>>>(px, gf, bf, pln);
    {
        dim3 grid((V + BN - 1) / BN, ROWS / BM);
        gemm_nt_kernel<<<grid, 256>>>(pln, Wun, bun, out, ROWS, V, D, 0);
    }
}

// round 7
// speedup vs baseline: 1.5120x; 1.5120x over previous
#include <cuda_runtime.h>
#include <cuda_bf16.h>
#include <cstdint>

// Problem constants
#define LNUM 8
#define D 1024
#define H 16
#define CH 64          // head dim
#define MSZ 4096
#define V 64
#define TMAX 2048
#define BB 4
#define TT 2048
#define ROWS (BB*TT)   // 8192
#define EPS 1e-5f

// ---------------- f32x2 packed helpers (sm_103a FFMA2 path) ------------------
typedef unsigned long long u64;

__device__ __forceinline__ void fma2(u64& d, u64 a, u64 b) {
    asm("fma.rn.f32x2 %0, %1, %2, %0;" : "+l"(d) : "l"(a), "l"(b));
}
__device__ __forceinline__ void mul2(u64& d, u64 a, u64 b) {
    asm("mul.rn.f32x2 %0, %1, %2;" : "=l"(d) : "l"(a), "l"(b));
}
__device__ __forceinline__ u64 pk2(float x, float y) {
    u64 r; asm("mov.b64 %0, {%1, %2};" : "=l"(r) : "f"(x), "f"(y)); return r;
}
__device__ __forceinline__ float2 upk(u64 v) {
    float2 r; asm("mov.b64 {%0, %1}, %2;" : "=f"(r.x), "=f"(r.y) : "l"(v)); return r;
}

// ---------------- scratch (device globals; no allocations allowed) ----------
__device__ float g_x[ROWS * D];
__device__ float g_h[ROWS * D];
__device__ float g_ln[ROWS * D];
__device__ float g_qkv[ROWS * 3 * D];
__device__ float g_mid[ROWS * MSZ];

// ---------------- embedding: x = toks @ Wtok^T + Wpos^T[:T] -----------------
__global__ __launch_bounds__(256) void embed_kernel(
    const float* __restrict__ toks, const float* __restrict__ Wtok,
    const float* __restrict__ Wpos, float* __restrict__ x)
{
    int bt = blockIdx.x;
    int t = bt % TT;
    __shared__ float tk[V];
    if (threadIdx.x < V) tk[threadIdx.x] = toks[(size_t)bt * V + threadIdx.x];
    __syncthreads();
    for (int d = threadIdx.x; d < D; d += 256) {
        float s = Wpos[(size_t)d * TMAX + t];
        const float* wr = Wtok + (size_t)d * V;
        #pragma unroll 16
        for (int v = 0; v < V; v++) s += tk[v] * wr[v];
        x[(size_t)bt * D + d] = s;
    }
}

// ---------------- layernorm over D=1024, one block per row ------------------
__global__ __launch_bounds__(256) void ln_kernel(
    const float* __restrict__ x, const float* __restrict__ g,
    const float* __restrict__ be, float* __restrict__ out)
{
    int row = blockIdx.x;
    const float* xr = x + (size_t)row * D;
    int tid = threadIdx.x;
    float v[4];
    float s = 0.f;
    #pragma unroll
    for (int i = 0; i < 4; i++) { v[i] = xr[tid + i * 256]; s += v[i]; }

    __shared__ float red[8];
    #pragma unroll
    for (int o = 16; o; o >>= 1) s += __shfl_xor_sync(0xffffffffu, s, o);
    if ((tid & 31) == 0) red[tid >> 5] = s;
    __syncthreads();
    if (tid < 32) {
        float t2 = (tid < 8) ? red[tid] : 0.f;
        #pragma unroll
        for (int o = 4; o; o >>= 1) t2 += __shfl_xor_sync(0xffffffffu, t2, o);
        if (tid == 0) red[0] = t2;
    }
    __syncthreads();
    float mean = red[0] * (1.f / D);
    __syncthreads();

    float s2 = 0.f;
    #pragma unroll
    for (int i = 0; i < 4; i++) { float d0 = v[i] - mean; s2 += d0 * d0; }
    #pragma unroll
    for (int o = 16; o; o >>= 1) s2 += __shfl_xor_sync(0xffffffffu, s2, o);
    if ((tid & 31) == 0) red[tid >> 5] = s2;
    __syncthreads();
    if (tid < 32) {
        float t2 = (tid < 8) ? red[tid] : 0.f;
        #pragma unroll
        for (int o = 4; o; o >>= 1) t2 += __shfl_xor_sync(0xffffffffu, t2, o);
        if (tid == 0) red[0] = t2;
    }
    __syncthreads();
    float var = red[0] * (1.f / D);
    float rstd = rsqrtf(var + EPS);

    float* orow = out + (size_t)row * D;
    #pragma unroll
    for (int i = 0; i < 4; i++) {
        int d0 = tid + i * 256;
        orow[d0] = (v[i] - mean) * rstd * g[d0] + be[d0];
    }
}

// ---------------- NT GEMM with FFMA2: C[M,N] = A[M,K]*B[N,K]^T ---------------
// 128x128x8 tiles, 256 threads, double-buffered smem, packed f32x2 inner loop.
#define BM 128
#define BN 128
#define BK 8
#define PITCH 132

// mode 0: C = acc (+bias) (opt relu)
// mode 1: C = add1 + addh + acc + bias   (fused residual; C may alias add1)
__global__ __launch_bounds__(256, 2) void gemm2_kernel(
    const float* __restrict__ A, const float* __restrict__ B,
    const float* __restrict__ bias, float* __restrict__ C,
    const float* __restrict__ add1, const float* __restrict__ addh,
    int N, int K, int relu, int mode)
{
    __shared__ float As[2][BK][PITCH];
    __shared__ float Bs[2][BK][PITCH];

    int tid = threadIdx.x;
    int tx = tid & 15, ty = tid >> 4;
    int rowA0 = blockIdx.y * BM;
    int colB0 = blockIdx.x * BN;

    int lr = tid >> 1;            // 0..127
    int lc = (tid & 1) * 4;       // 0 or 4
    const float* Ag = A + (size_t)(rowA0 + lr) * K + lc;
    int bn = colB0 + lr;
    bool bvalid = (bn < N);
    const float* Bg = B + (size_t)(bvalid ? bn : 0) * K + lc;

    u64 acc2[4][8];
    #pragma unroll
    for (int p = 0; p < 4; p++)
        #pragma unroll
        for (int j = 0; j < 8; j++) acc2[p][j] = 0ull;

    const int nt = K / BK;
    float4 na = *(const float4*)Ag;
    float4 nb = bvalid ? *(const float4*)Bg : make_float4(0.f, 0.f, 0.f, 0.f);
    As[0][lc + 0][lr] = na.x; As[0][lc + 1][lr] = na.y;
    As[0][lc + 2][lr] = na.z; As[0][lc + 3][lr] = na.w;
    Bs[0][lc + 0][lr] = nb.x; Bs[0][lc + 1][lr] = nb.y;
    Bs[0][lc + 2][lr] = nb.z; Bs[0][lc + 3][lr] = nb.w;
    __syncthreads();

    int cur = 0;
    for (int it = 0; it < nt; it++) {
        bool has = (it + 1 < nt);
        if (has) {
            na = *(const float4*)(Ag + (it + 1) * BK);
            nb = bvalid ? *(const float4*)(Bg + (it + 1) * BK)
                        : make_float4(0.f, 0.f, 0.f, 0.f);
        }
        #pragma unroll
        for (int k = 0; k < BK; k++) {
            ulonglong2 aA = *(const ulonglong2*)&As[cur][k][ty * 8];
            ulonglong2 aB = *(const ulonglong2*)&As[cur][k][ty * 8 + 4];
            float4 b0 = *(const float4*)&Bs[cur][k][tx * 8];
            float4 b1 = *(const float4*)&Bs[cur][k][tx * 8 + 4];
            u64 bb[8];
            bb[0] = pk2(b0.x, b0.x); bb[1] = pk2(b0.y, b0.y);
            bb[2] = pk2(b0.z, b0.z); bb[3] = pk2(b0.w, b0.w);
            bb[4] = pk2(b1.x, b1.x); bb[5] = pk2(b1.y, b1.y);
            bb[6] = pk2(b1.z, b1.z); bb[7] = pk2(b1.w, b1.w);
            #pragma unroll
            for (int j = 0; j < 8; j++) {
                fma2(acc2[0][j], aA.x, bb[j]);
                fma2(acc2[1][j], aA.y, bb[j]);
                fma2(acc2[2][j], aB.x, bb[j]);
                fma2(acc2[3][j], aB.y, bb[j]);
            }
        }
        if (has) {
            int nxt = cur ^ 1;
            As[nxt][lc + 0][lr] = na.x; As[nxt][lc + 1][lr] = na.y;
            As[nxt][lc + 2][lr] = na.z; As[nxt][lc + 3][lr] = na.w;
            Bs[nxt][lc + 0][lr] = nb.x; Bs[nxt][lc + 1][lr] = nb.y;
            Bs[nxt][lc + 2][lr] = nb.z; Bs[nxt][lc + 3][lr] = nb.w;
        }
        __syncthreads();
        cur ^= 1;
    }

    // epilogue: pair p covers rows ty*8 + 2p, +2p+1
    #pragma unroll
    for (int p = 0; p < 4; p++) {
        int r0 = rowA0 + ty * 8 + 2 * p;
        #pragma unroll
        for (int j = 0; j < 8; j++) {
            int col = colB0 + tx * 8 + j;
            if (col < N) {
                float2 f = upk(acc2[p][j]);
                float bc = bias ? bias[col] : 0.f;
                float v0 = f.x + bc, v1 = f.y + bc;
                if (relu) { v0 = fmaxf(v0, 0.f); v1 = fmaxf(v1, 0.f); }
                if (mode == 1) {
                    size_t i0 = (size_t)r0 * N + col;
                    size_t i1 = (size_t)(r0 + 1) * N + col;
                    v0 += add1[i0] + addh[i0];
                    v1 += add1[i1] + addh[i1];
                    C[i0] = v0; C[i1] = v1;
                } else {
                    C[(size_t)r0 * N + col] = v0;
                    C[(size_t)(r0 + 1) * N + col] = v1;
                }
            }
        }
    }
}

// ---------------- causal attention, f32x2, fused residual --------------------
// qkv row layout per (b,t): [H][3*CH] = q|k|v per head. Writes h = x + attn.
#define TS 32
__global__ __launch_bounds__(128) void attn_kernel(
    const float* __restrict__ qkv, const float* __restrict__ xres,
    float* __restrict__ out)
{
    int qt0 = blockIdx.x * 128;
    int h = blockIdx.y, b = blockIdx.z;
    int tid = threadIdx.x;
    int t = qt0 + tid;

    __shared__ float Ks[TS][CH];
    __shared__ float Vs[TS][CH];
    __shared__ float Ss[128][TS + 1];

    const size_t rstride = 3 * D;
    const float* base = qkv + (size_t)b * TT * rstride + (size_t)h * 3 * CH;

    u64 q2[CH / 2];
    {
        const float* qr = base + (size_t)t * rstride;
        #pragma unroll
        for (int c = 0; c < CH / 2; c++)
            q2[c] = pk2(qr[2 * c] * 0.125f, qr[2 * c + 1] * 0.125f);
    }

    u64 acc2[CH / 2];
    #pragma unroll
    for (int c = 0; c < CH / 2; c++) acc2[c] = 0ull;
    float m = -1e30f, l = 0.f;

    int smax = qt0 + 127;
    for (int s0 = 0; s0 <= smax; s0 += TS) {
        for (int i = tid; i < TS * CH; i += 128) {
            int s = i >> 6, c = i & 63;
            const float* kr = base + (size_t)(s0 + s) * rstride;
            Ks[s][c] = kr[CH + c];
            Vs[s][c] = kr[2 * CH + c];
        }
        __syncthreads();

        float mt = -1e30f;
        for (int s = 0; s < TS; s++) {
            const u64* k2 = (const u64*)&Ks[s][0];
            u64 d2 = 0ull;
            #pragma unroll
            for (int c = 0; c < CH / 2; c++) fma2(d2, q2[c], k2[c]);
            float2 dd = upk(d2);
            float sc = dd.x + dd.y;
            if (s0 + s > t) sc = -1e30f;
            Ss[tid][s] = sc;
            mt = fmaxf(mt, sc);
        }
        float mn = fmaxf(m, mt);
        float corr = __expf(m - mn);
        u64 corr2 = pk2(corr, corr);
        l *= corr;
        #pragma unroll
        for (int c = 0; c < CH / 2; c++) mul2(acc2[c], acc2[c], corr2);
        for (int s = 0; s < TS; s++) {
            float p = __expf(Ss[tid][s] - mn);
            l += p;
            u64 p2 = pk2(p, p);
            const u64* v2 = (const u64*)&Vs[s][0];
            #pragma unroll
            for (int c = 0; c < CH / 2; c++) fma2(acc2[c], p2, v2[c]);
        }
        m = mn;
        __syncthreads();
    }

    float inv = 1.f / l;
    size_t obase = ((size_t)b * TT + t) * D + h * CH;
    float* o = out + obase;
    const float* xr = xres + obase;
    #pragma unroll
    for (int c = 0; c < CH / 2; c++) {
        float2 a = upk(acc2[c]);
        o[2 * c]     = xr[2 * c]     + a.x * inv;
        o[2 * c + 1] = xr[2 * c + 1] + a.y * inv;
    }
}

// ---------------- driver -----------------------------------------------------
extern "C" void kernel_launch(void* const* d_in, const int* in_sizes, int n_in,
                              void* d_out, int out_size)
{
    const float* toks  = (const float*)d_in[0];
    const float* W_tok = (const float*)d_in[1];
    const float* W_pos = (const float*)d_in[2];
    const float* Wqkv  = (const float*)d_in[3];
    const float* g1    = (const float*)d_in[4];
    const float* be1   = (const float*)d_in[5];
    const float* W1    = (const float*)d_in[6];
    const float* bm1   = (const float*)d_in[7];
    const float* W2    = (const float*)d_in[8];
    const float* bm2   = (const float*)d_in[9];
    const float* g2    = (const float*)d_in[10];
    const float* be2   = (const float*)d_in[11];
    const float* gf    = (const float*)d_in[12];
    const float* bf    = (const float*)d_in[13];
    const float* Wun   = (const float*)d_in[14];
    const float* bun   = (const float*)d_in[15];
    float* out = (float*)d_out;

    float *px, *ph, *pln, *pqkv, *pmid;
    cudaGetSymbolAddress((void**)&px,   g_x);
    cudaGetSymbolAddress((void**)&ph,   g_h);
    cudaGetSymbolAddress((void**)&pln,  g_ln);
    cudaGetSymbolAddress((void**)&pqkv, g_qkv);
    cudaGetSymbolAddress((void**)&pmid, g_mid);

    // embedding
    embed_kernel<<<ROWS, 256>>>(toks, W_tok, W_pos, px);

    for (int l = 0; l < LNUM; l++) {
        const float* wqkv = Wqkv + (size_t)l * 3 * D * D;
        const float* w1   = W1   + (size_t)l * MSZ * D;
        const float* w2   = W2   + (size_t)l * D * MSZ;

        // ln1 -> qkv gemm -> attention (fused h = x + attn)
        ln_kernel<<<ROWS, 256>>>(px, g1 + l * D, be1 + l * D, pln);
        {
            dim3 grid(3 * D / BN, ROWS / BM);
            gemm2_kernel<<<grid, 256>>>(pln, wqkv, nullptr, pqkv,
                                        nullptr, nullptr, 3 * D, D, 0, 0);
        }
        {
            dim3 grid(TT / 128, H, BB);
            attn_kernel<<<grid, 128>>>(pqkv, px, ph);
        }

        // ln2 -> mlp (mlp2 fuses x = x + h + mlp + bias)
        ln_kernel<<<ROWS, 256>>>(ph, g2 + l * D, be2 + l * D, pln);
        {
            dim3 grid(MSZ / BN, ROWS / BM);
            gemm2_kernel<<<grid, 256>>>(pln, w1, bm1 + (size_t)l * MSZ, pmid,
                                        nullptr, nullptr, MSZ, D, 1, 0);
        }
        {
            dim3 grid(D / BN, ROWS / BM);
            gemm2_kernel<<<grid, 256>>>(pmid, w2, bm2 + (size_t)l * D, px,
                                        px, ph, D, MSZ, 0, 1);
        }
    }

    // final layernorm + unembed
    ln_kernel<<<ROWS, 256>>>(px, gf, bf, pln);
    {
        dim3 grid((V + BN - 1) / BN, ROWS / BM);
        gemm2_kernel<<<grid, 256>>>(pln, Wun, bun, out,
                                    nullptr, nullptr, V, D, 0, 0);
    }
}

// round 9
// speedup vs baseline: 1.7726x; 1.1724x over previous
#include <cuda_runtime.h>
#include <cuda_bf16.h>
#include <cstdint>

// Problem constants
#define LNUM 8
#define D 1024
#define H 16
#define CH 64
#define MSZ 4096
#define V 64
#define TMAX 2048
#define BB 4
#define TT 2048
#define ROWS (BB*TT)   // 8192
#define EPS 1e-5f

typedef unsigned long long u64;

// ---------------- f32x2 packed helpers (attention) ---------------------------
__device__ __forceinline__ void fma2(u64& d, u64 a, u64 b) {
    asm("fma.rn.f32x2 %0, %1, %2, %0;" : "+l"(d) : "l"(a), "l"(b));
}
__device__ __forceinline__ void mul2(u64& d, u64 a, u64 b) {
    asm("mul.rn.f32x2 %0, %1, %2;" : "=l"(d) : "l"(a), "l"(b));
}
__device__ __forceinline__ u64 pk2(float x, float y) {
    u64 r; asm("mov.b64 %0, {%1, %2};" : "=l"(r) : "f"(x), "f"(y)); return r;
}
__device__ __forceinline__ float2 upk(u64 v) {
    float2 r; asm("mov.b64 {%0, %1}, %2;" : "=f"(r.x), "=f"(r.y) : "l"(v)); return r;
}

__device__ __forceinline__ uint32_t smem_to_u32(const void* p) {
    uint32_t a;
    asm("{ .reg .u64 t; cvta.to.shared.u64 t, %1; cvt.u32.u64 %0, t; }" : "=r"(a) : "l"(p));
    return a;
}

// ---------------- mma.sync helpers (sm_80+ path, works on plain sm_103) ------
__device__ __forceinline__ void ldsm_x4(uint32_t& r0, uint32_t& r1, uint32_t& r2, uint32_t& r3, uint32_t addr) {
    asm volatile("ldmatrix.sync.aligned.m8n8.x4.shared.b16 {%0,%1,%2,%3}, [%4];"
        : "=r"(r0), "=r"(r1), "=r"(r2), "=r"(r3) : "r"(addr));
}
__device__ __forceinline__ void ldsm_x2(uint32_t& r0, uint32_t& r1, uint32_t addr) {
    asm volatile("ldmatrix.sync.aligned.m8n8.x2.shared.b16 {%0,%1}, [%2];"
        : "=r"(r0), "=r"(r1) : "r"(addr));
}
__device__ __forceinline__ void mma_bf16(float* d, const uint32_t* a, const uint32_t* b) {
    asm volatile(
        "mma.sync.aligned.m16n8k16.row.col.f32.bf16.bf16.f32 "
        "{%0,%1,%2,%3}, {%4,%5,%6,%7}, {%8,%9}, {%0,%1,%2,%3};"
        : "+f"(d[0]), "+f"(d[1]), "+f"(d[2]), "+f"(d[3])
        : "r"(a[0]), "r"(a[1]), "r"(a[2]), "r"(a[3]), "r"(b[0]), "r"(b[1]));
}
#define CP_ASYNC16(dst, src) \
    asm volatile("cp.async.ca.shared.global [%0], [%1], 16;" :: "r"(dst), "l"(src) : "memory")
#define CP_COMMIT() asm volatile("cp.async.commit_group;" ::: "memory")
#define CP_WAIT(n)  asm volatile("cp.async.wait_group %0;" :: "n"(n) : "memory")

// ---------------- scratch (device globals) -----------------------------------
__device__ float g_x[ROWS * D];
__device__ float g_h[ROWS * D];
__device__ float g_qkv[ROWS * 3 * D];
__device__ __nv_bfloat16 g_ln_hi[ROWS * D];
__device__ __nv_bfloat16 g_ln_lo[ROWS * D];
__device__ __nv_bfloat16 g_mid_hi[ROWS * MSZ];
__device__ __nv_bfloat16 g_mid_lo[ROWS * MSZ];
__device__ __nv_bfloat16 g_wqkv_hi[LNUM * 3 * D * D];
__device__ __nv_bfloat16 g_wqkv_lo[LNUM * 3 * D * D];
__device__ __nv_bfloat16 g_w1_hi[LNUM * MSZ * D];
__device__ __nv_bfloat16 g_w1_lo[LNUM * MSZ * D];
__device__ __nv_bfloat16 g_w2_hi[LNUM * D * MSZ];
__device__ __nv_bfloat16 g_w2_lo[LNUM * D * MSZ];
__device__ __nv_bfloat16 g_wun_hi[V * D];
__device__ __nv_bfloat16 g_wun_lo[V * D];

// ---------------- weight split fp32 -> bf16 hi/lo ----------------------------
__global__ __launch_bounds__(256) void cvt_kernel(
    const float* __restrict__ w, __nv_bfloat16* __restrict__ hi,
    __nv_bfloat16* __restrict__ lo, int n)
{
    int i = blockIdx.x * 256 + threadIdx.x;
    if (i < n) {
        float v = w[i];
        __nv_bfloat16 h = __float2bfloat16_rn(v);
        hi[i] = h;
        lo[i] = __float2bfloat16_rn(v - __bfloat162float(h));
    }
}

// ---------------- embedding --------------------------------------------------
__global__ __launch_bounds__(256) void embed_kernel(
    const float* __restrict__ toks, const float* __restrict__ Wtok,
    const float* __restrict__ Wpos, float* __restrict__ x)
{
    int bt = blockIdx.x;
    int t = bt % TT;
    __shared__ float tk[V];
    if (threadIdx.x < V) tk[threadIdx.x] = toks[(size_t)bt * V + threadIdx.x];
    __syncthreads();
    for (int d = threadIdx.x; d < D; d += 256) {
        float s = Wpos[(size_t)d * TMAX + t];
        const float* wr = Wtok + (size_t)d * V;
        #pragma unroll 16
        for (int v = 0; v < V; v++) s += tk[v] * wr[v];
        x[(size_t)bt * D + d] = s;
    }
}

// ---------------- layernorm -> bf16 hi/lo outputs ----------------------------
__global__ __launch_bounds__(256) void ln_kernel(
    const float* __restrict__ x, const float* __restrict__ g,
    const float* __restrict__ be, __nv_bfloat16* __restrict__ ohi,
    __nv_bfloat16* __restrict__ olo)
{
    int row = blockIdx.x;
    const float* xr = x + (size_t)row * D;
    int tid = threadIdx.x;
    float v[4];
    float s = 0.f;
    #pragma unroll
    for (int i = 0; i < 4; i++) { v[i] = xr[tid + i * 256]; s += v[i]; }

    __shared__ float red[8];
    #pragma unroll
    for (int o = 16; o; o >>= 1) s += __shfl_xor_sync(0xffffffffu, s, o);
    if ((tid & 31) == 0) red[tid >> 5] = s;
    __syncthreads();
    if (tid < 32) {
        float t2 = (tid < 8) ? red[tid] : 0.f;
        #pragma unroll
        for (int o = 4; o; o >>= 1) t2 += __shfl_xor_sync(0xffffffffu, t2, o);
        if (tid == 0) red[0] = t2;
    }
    __syncthreads();
    float mean = red[0] * (1.f / D);
    __syncthreads();

    float s2 = 0.f;
    #pragma unroll
    for (int i = 0; i < 4; i++) { float d0 = v[i] - mean; s2 += d0 * d0; }
    #pragma unroll
    for (int o = 16; o; o >>= 1) s2 += __shfl_xor_sync(0xffffffffu, s2, o);
    if ((tid & 31) == 0) red[tid >> 5] = s2;
    __syncthreads();
    if (tid < 32) {
        float t2 = (tid < 8) ? red[tid] : 0.f;
        #pragma unroll
        for (int o = 4; o; o >>= 1) t2 += __shfl_xor_sync(0xffffffffu, t2, o);
        if (tid == 0) red[0] = t2;
    }
    __syncthreads();
    float var = red[0] * (1.f / D);
    float rstd = rsqrtf(var + EPS);

    size_t base = (size_t)row * D;
    #pragma unroll
    for (int i = 0; i < 4; i++) {
        int d0 = tid + i * 256;
        float vv = (v[i] - mean) * rstd * g[d0] + be[d0];
        __nv_bfloat16 hh = __float2bfloat16_rn(vv);
        ohi[base + d0] = hh;
        olo[base + d0] = __float2bfloat16_rn(vv - __bfloat162float(hh));
    }
}

// ---------------- split-bf16 NT GEMM via mma.sync ----------------------------
// C[M,N] = A[M,K]*B[N,K]^T via Ahi*Bhi + Ahi*Blo + Alo*Bhi, fp32 reg acc.
// 128x128 tile, 256 thr (2x4 warps, 64x32 per warp), BK=32, cp.async 2-buf.
#define GT 256
#define TILE 128
#define BKC 32
#define PITCHB 80                  // bytes per smem row (64 data + 16 pad)
#define ABYTES (128 * PITCHB)      // 10240
#define BUFBYTES (4 * ABYTES)      // 40960 : AH AL BH BL
#define SMEM_TOT (2 * BUFBYTES)    // 81920

// mode 0: C = acc (+bias) (opt relu), fp32
// mode 1: v = relu(acc + bias); write bf16 split to Ohi/Olo
// mode 2: C = acc + bias + add1 + addh, fp32 (C may alias add1)
__global__ __launch_bounds__(GT) void gemm_mma(
    const __nv_bfloat16* __restrict__ Ahi, const __nv_bfloat16* __restrict__ Alo,
    const __nv_bfloat16* __restrict__ Bhi, const __nv_bfloat16* __restrict__ Blo,
    const float* __restrict__ bias, float* __restrict__ C,
    const float* __restrict__ add1, const float* __restrict__ addh,
    __nv_bfloat16* __restrict__ Ohi, __nv_bfloat16* __restrict__ Olo,
    int N, int K, int relu, int mode)
{
    extern __shared__ char sm[];
    uint32_t sb = smem_to_u32(sm);
    int tid = threadIdx.x;
    int wid = tid >> 5, lane = tid & 31;
    int wm = wid & 1, wn = wid >> 1;             // 2 x 4 warp grid
    int rowA0 = blockIdx.y * TILE;
    int colB0 = blockIdx.x * TILE;

    float acc[4][4][4];
    #pragma unroll
    for (int i = 0; i < 4; i++)
        #pragma unroll
        for (int j = 0; j < 4; j++)
            #pragma unroll
            for (int k = 0; k < 4; k++) acc[i][j][k] = 0.f;

    // per-thread load mapping: idx -> (row, 8-col group)
    int l_r0 = tid >> 2;                 // rows 0..63   (idx = tid)
    int l_r1 = (256 + tid) >> 2;         // rows 64..127 (idx = 256+tid)
    int l_c0 = (tid & 3) * 8;            // bf16 col 0,8,16,24

    const int nch = K / BKC;

    // issue async loads of chunk c into buffer b
    auto issue = [&](int c, int b) {
        int k0 = c * BKC;
        uint32_t base = sb + b * BUFBYTES;
        #pragma unroll
        for (int i = 0; i < 2; i++) {
            int r = i ? l_r1 : l_r0;
            uint32_t doff = (uint32_t)(r * PITCHB + l_c0 * 2);
            size_t ga = (size_t)(rowA0 + r) * K + k0 + l_c0;
            int br = colB0 + r; if (br > N - 1) br = N - 1;
            size_t gb = (size_t)br * K + k0 + l_c0;
            CP_ASYNC16(base + 0 * ABYTES + doff, Ahi + ga);
            CP_ASYNC16(base + 1 * ABYTES + doff, Alo + ga);
            CP_ASYNC16(base + 2 * ABYTES + doff, Bhi + gb);
            CP_ASYNC16(base + 3 * ABYTES + doff, Blo + gb);
        }
        CP_COMMIT();
    };

    issue(0, 0);

    // ldmatrix lane addressing
    uint32_t a_off = (uint32_t)((wm * 64 + (lane & 15)) * PITCHB + (lane >> 4) * 16);
    uint32_t b_off = (uint32_t)((wn * 32 + (lane & 7)) * PITCHB + ((lane >> 3) & 1) * 16);

    for (int c = 0; c < nch; c++) {
        int b = c & 1;
        if (c + 1 < nch) { issue(c + 1, b ^ 1); CP_WAIT(1); }
        else             { CP_WAIT(0); }
        __syncthreads();

        uint32_t sAH = sb + b * BUFBYTES + 0 * ABYTES;
        uint32_t sAL = sb + b * BUFBYTES + 1 * ABYTES;
        uint32_t sBH = sb + b * BUFBYTES + 2 * ABYTES;
        uint32_t sBL = sb + b * BUFBYTES + 3 * ABYTES;

        #pragma unroll
        for (int kk = 0; kk < 2; kk++) {
            uint32_t ah[4][4], al[4][4], bh[4][2], bl[4][2];
            #pragma unroll
            for (int mt = 0; mt < 4; mt++) {
                uint32_t ao = a_off + mt * 16 * PITCHB + kk * 32;
                ldsm_x4(ah[mt][0], ah[mt][1], ah[mt][2], ah[mt][3], sAH + ao);
                ldsm_x4(al[mt][0], al[mt][1], al[mt][2], al[mt][3], sAL + ao);
            }
            #pragma unroll
            for (int nt = 0; nt < 4; nt++) {
                uint32_t bo = b_off + nt * 8 * PITCHB + kk * 32;
                ldsm_x2(bh[nt][0], bh[nt][1], sBH + bo);
                ldsm_x2(bl[nt][0], bl[nt][1], sBL + bo);
            }
            #pragma unroll
            for (int mt = 0; mt < 4; mt++)
                #pragma unroll
                for (int nt = 0; nt < 4; nt++) {
                    mma_bf16(acc[mt][nt], ah[mt], bh[nt]);
                    mma_bf16(acc[mt][nt], ah[mt], bl[nt]);
                    mma_bf16(acc[mt][nt], al[mt], bh[nt]);
                }
        }
        __syncthreads();
    }

    // epilogue
    int r_base = rowA0 + wm * 64 + (lane >> 2);
    int c_base = colB0 + wn * 32 + (lane & 3) * 2;
    #pragma unroll
    for (int mt = 0; mt < 4; mt++) {
        #pragma unroll
        for (int half = 0; half < 2; half++) {
            int row = r_base + mt * 16 + half * 8;
            #pragma unroll
            for (int nt = 0; nt < 4; nt++) {
                int col = c_base + nt * 8;
                if (col + 1 < N || col < N) {
                    float v0 = acc[mt][nt][half * 2 + 0];
                    float v1 = acc[mt][nt][half * 2 + 1];
                    if (bias) { v0 += bias[col]; if (col + 1 < N) v1 += bias[col + 1]; }
                    if (relu) { v0 = fmaxf(v0, 0.f); v1 = fmaxf(v1, 0.f); }
                    size_t i0 = (size_t)row * N + col;
                    if (mode == 2) {
                        v0 += add1[i0] + addh[i0];
                        if (col + 1 < N) v1 += add1[i0 + 1] + addh[i0 + 1];
                    }
                    if (mode == 1) {
                        __nv_bfloat16 h0 = __float2bfloat16_rn(v0);
                        Ohi[i0] = h0;
                        Olo[i0] = __float2bfloat16_rn(v0 - __bfloat162float(h0));
                        if (col + 1 < N) {
                            __nv_bfloat16 h1 = __float2bfloat16_rn(v1);
                            Ohi[i0 + 1] = h1;
                            Olo[i0 + 1] = __float2bfloat16_rn(v1 - __bfloat162float(h1));
                        }
                    } else {
                        C[i0] = v0;
                        if (col + 1 < N) C[i0 + 1] = v1;
                    }
                }
            }
        }
    }
}

// ---------------- causal attention, f32x2, fused residual --------------------
#define TS 32
__global__ __launch_bounds__(128) void attn_kernel(
    const float* __restrict__ qkv, const float* __restrict__ xres,
    float* __restrict__ out)
{
    int qt0 = blockIdx.x * 128;
    int h = blockIdx.y, b = blockIdx.z;
    int tid = threadIdx.x;
    int t = qt0 + tid;

    __shared__ float Ks[TS][CH];
    __shared__ float Vs[TS][CH];
    __shared__ float Ss[128][TS + 1];

    const size_t rstride = 3 * D;
    const float* base = qkv + (size_t)b * TT * rstride + (size_t)h * 3 * CH;

    u64 q2[CH / 2];
    {
        const float* qr = base + (size_t)t * rstride;
        #pragma unroll
        for (int c = 0; c < CH / 2; c++)
            q2[c] = pk2(qr[2 * c] * 0.125f, qr[2 * c + 1] * 0.125f);
    }

    u64 acc2[CH / 2];
    #pragma unroll
    for (int c = 0; c < CH / 2; c++) acc2[c] = 0ull;
    float m = -1e30f, l = 0.f;

    int smax = qt0 + 127;
    for (int s0 = 0; s0 <= smax; s0 += TS) {
        for (int i = tid; i < TS * CH; i += 128) {
            int s = i >> 6, c = i & 63;
            const float* kr = base + (size_t)(s0 + s) * rstride;
            Ks[s][c] = kr[CH + c];
            Vs[s][c] = kr[2 * CH + c];
        }
        __syncthreads();

        float mt = -1e30f;
        for (int s = 0; s < TS; s++) {
            const u64* k2 = (const u64*)&Ks[s][0];
            u64 d2 = 0ull;
            #pragma unroll
            for (int c = 0; c < CH / 2; c++) fma2(d2, q2[c], k2[c]);
            float2 dd = upk(d2);
            float sc = dd.x + dd.y;
            if (s0 + s > t) sc = -1e30f;
            Ss[tid][s] = sc;
            mt = fmaxf(mt, sc);
        }
        float mn = fmaxf(m, mt);
        float corr = __expf(m - mn);
        u64 corr2 = pk2(corr, corr);
        l *= corr;
        #pragma unroll
        for (int c = 0; c < CH / 2; c++) mul2(acc2[c], acc2[c], corr2);
        for (int s = 0; s < TS; s++) {
            float p = __expf(Ss[tid][s] - mn);
            l += p;
            u64 p2 = pk2(p, p);
            const u64* v2 = (const u64*)&Vs[s][0];
            #pragma unroll
            for (int c = 0; c < CH / 2; c++) fma2(acc2[c], p2, v2[c]);
        }
        m = mn;
        __syncthreads();
    }

    float inv = 1.f / l;
    size_t obase = ((size_t)b * TT + t) * D + h * CH;
    float* o = out + obase;
    const float* xr = xres + obase;
    #pragma unroll
    for (int c = 0; c < CH / 2; c++) {
        float2 a = upk(acc2[c]);
        o[2 * c]     = xr[2 * c]     + a.x * inv;
        o[2 * c + 1] = xr[2 * c + 1] + a.y * inv;
    }
}

// ---------------- driver -----------------------------------------------------
extern "C" void kernel_launch(void* const* d_in, const int* in_sizes, int n_in,
                              void* d_out, int out_size)
{
    const float* toks  = (const float*)d_in[0];
    const float* W_tok = (const float*)d_in[1];
    const float* W_pos = (const float*)d_in[2];
    const float* Wqkv  = (const float*)d_in[3];
    const float* g1    = (const float*)d_in[4];
    const float* be1   = (const float*)d_in[5];
    const float* W1    = (const float*)d_in[6];
    const float* bm1   = (const float*)d_in[7];
    const float* W2    = (const float*)d_in[8];
    const float* bm2   = (const float*)d_in[9];
    const float* g2    = (const float*)d_in[10];
    const float* be2   = (const float*)d_in[11];
    const float* gf    = (const float*)d_in[12];
    const float* bf    = (const float*)d_in[13];
    const float* Wun   = (const float*)d_in[14];
    const float* bun   = (const float*)d_in[15];
    float* out = (float*)d_out;

    float *px, *ph, *pqkv;
    __nv_bfloat16 *plnh, *plnl, *pmidh, *pmidl;
    __nv_bfloat16 *pwqh, *pwql, *pw1h, *pw1l, *pw2h, *pw2l, *pwuh, *pwul;
    cudaGetSymbolAddress((void**)&px,    g_x);
    cudaGetSymbolAddress((void**)&ph,    g_h);
    cudaGetSymbolAddress((void**)&pqkv,  g_qkv);
    cudaGetSymbolAddress((void**)&plnh,  g_ln_hi);
    cudaGetSymbolAddress((void**)&plnl,  g_ln_lo);
    cudaGetSymbolAddress((void**)&pmidh, g_mid_hi);
    cudaGetSymbolAddress((void**)&pmidl, g_mid_lo);
    cudaGetSymbolAddress((void**)&pwqh,  g_wqkv_hi);
    cudaGetSymbolAddress((void**)&pwql,  g_wqkv_lo);
    cudaGetSymbolAddress((void**)&pw1h,  g_w1_hi);
    cudaGetSymbolAddress((void**)&pw1l,  g_w1_lo);
    cudaGetSymbolAddress((void**)&pw2h,  g_w2_hi);
    cudaGetSymbolAddress((void**)&pw2l,  g_w2_lo);
    cudaGetSymbolAddress((void**)&pwuh,  g_wun_hi);
    cudaGetSymbolAddress((void**)&pwul,  g_wun_lo);

    cudaFuncSetAttribute(gemm_mma, cudaFuncAttributeMaxDynamicSharedMemorySize, SMEM_TOT);

    // split weights to bf16 hi/lo
    {
        int n;
        n = LNUM * 3 * D * D; cvt_kernel<<<(n + 255) / 256, 256>>>(Wqkv, pwqh, pwql, n);
        n = LNUM * MSZ * D;   cvt_kernel<<<(n + 255) / 256, 256>>>(W1, pw1h, pw1l, n);
        n = LNUM * D * MSZ;   cvt_kernel<<<(n + 255) / 256, 256>>>(W2, pw2h, pw2l, n);
        n = V * D;            cvt_kernel<<<(n + 255) / 256, 256>>>(Wun, pwuh, pwul, n);
    }

    // embedding
    embed_kernel<<<ROWS, 256>>>(toks, W_tok, W_pos, px);

    for (int l = 0; l < LNUM; l++) {
        __nv_bfloat16* wqh = pwqh + (size_t)l * 3 * D * D;
        __nv_bfloat16* wql = pwql + (size_t)l * 3 * D * D;
        __nv_bfloat16* w1h = pw1h + (size_t)l * MSZ * D;
        __nv_bfloat16* w1l = pw1l + (size_t)l * MSZ * D;
        __nv_bfloat16* w2h = pw2h + (size_t)l * D * MSZ;
        __nv_bfloat16* w2l = pw2l + (size_t)l * D * MSZ;

        // ln1 -> qkv gemm (fp32 out) -> attention (fused h = x + attn)
        ln_kernel<<<ROWS, 256>>>(px, g1 + l * D, be1 + l * D, plnh, plnl);
        {
            dim3 grid(3 * D / TILE, ROWS / TILE);
            gemm_mma<<<grid, GT, SMEM_TOT>>>(plnh, plnl, wqh, wql, nullptr, pqkv,
                                             nullptr, nullptr, nullptr, nullptr,
                                             3 * D, D, 0, 0);
        }
        {
            dim3 grid(TT / 128, H, BB);
            attn_kernel<<<grid, 128>>>(pqkv, px, ph);
        }

        // ln2 -> mlp1 (relu, bf16 split out) -> mlp2 (fused x = x + h + mlp)
        ln_kernel<<<ROWS, 256>>>(ph, g2 + l * D, be2 + l * D, plnh, plnl);
        {
            dim3 grid(MSZ / TILE, ROWS / TILE);
            gemm_mma<<<grid, GT, SMEM_TOT>>>(plnh, plnl, w1h, w1l,
                                             bm1 + (size_t)l * MSZ, nullptr,
                                             nullptr, nullptr, pmidh, pmidl,
                                             MSZ, D, 1, 1);
        }
        {
            dim3 grid(D / TILE, ROWS / TILE);
            gemm_mma<<<grid, GT, SMEM_TOT>>>(pmidh, pmidl, w2h, w2l,
                                             bm2 + (size_t)l * D, px,
                                             px, ph, nullptr, nullptr,
                                             D, MSZ, 0, 2);
        }
    }

    // final layernorm + unembed (N=64)
    ln_kernel<<<ROWS, 256>>>(px, gf, bf, plnh, plnl);
    {
        dim3 grid(1, ROWS / TILE);
        gemm_mma<<<grid, GT, SMEM_TOT>>>(plnh, plnl, pwuh, pwul, bun, out,
                                         nullptr, nullptr, nullptr, nullptr,
                                         V, D, 0, 0);
    }
}

// round 11
// speedup vs baseline: 4.1728x; 2.3540x over previous
#include <cuda_runtime.h>
#include <cuda_bf16.h>
#include <cstdint>
#include <cstring>

// Problem constants
#define LNUM 8
#define D 1024
#define H 16
#define CH 64
#define MSZ 4096
#define V 64
#define TMAX 2048
#define BB 4
#define TT 2048
#define ROWS (BB*TT)   // 8192
#define EPS 1e-5f

typedef unsigned long long u64;

__device__ __forceinline__ uint32_t smem_to_u32(const void* p) {
    uint32_t a;
    asm("{ .reg .u64 t; cvta.to.shared.u64 t, %1; cvt.u32.u64 %0, t; }" : "=r"(a) : "l"(p));
    return a;
}

// ---------------- mma.sync helpers ------------------------------------------
__device__ __forceinline__ void ldsm_x4(uint32_t& r0, uint32_t& r1, uint32_t& r2, uint32_t& r3, uint32_t addr) {
    asm volatile("ldmatrix.sync.aligned.m8n8.x4.shared.b16 {%0,%1,%2,%3}, [%4];"
        : "=r"(r0), "=r"(r1), "=r"(r2), "=r"(r3) : "r"(addr));
}
__device__ __forceinline__ void ldsm_x2(uint32_t& r0, uint32_t& r1, uint32_t addr) {
    asm volatile("ldmatrix.sync.aligned.m8n8.x2.shared.b16 {%0,%1}, [%2];"
        : "=r"(r0), "=r"(r1) : "r"(addr));
}
__device__ __forceinline__ void ldsm_x2t(uint32_t& r0, uint32_t& r1, uint32_t addr) {
    asm volatile("ldmatrix.sync.aligned.m8n8.x2.trans.shared.b16 {%0,%1}, [%2];"
        : "=r"(r0), "=r"(r1) : "r"(addr));
}
__device__ __forceinline__ void mma_bf16(float* d, const uint32_t* a, const uint32_t* b) {
    asm volatile(
        "mma.sync.aligned.m16n8k16.row.col.f32.bf16.bf16.f32 "
        "{%0,%1,%2,%3}, {%4,%5,%6,%7}, {%8,%9}, {%0,%1,%2,%3};"
        : "+f"(d[0]), "+f"(d[1]), "+f"(d[2]), "+f"(d[3])
        : "r"(a[0]), "r"(a[1]), "r"(a[2]), "r"(a[3]), "r"(b[0]), "r"(b[1]));
}
#define CP_ASYNC16(dst, src) \
    asm volatile("cp.async.ca.shared.global [%0], [%1], 16;" :: "r"(dst), "l"(src) : "memory")
#define CP_COMMIT() asm volatile("cp.async.commit_group;" ::: "memory")
#define CP_WAIT(n)  asm volatile("cp.async.wait_group %0;" :: "n"(n) : "memory")

// pack two floats' bf16 roundings: low = v0, high = v1
__device__ __forceinline__ uint32_t pack_hi(float v0, float v1) {
    __nv_bfloat162 t;
    t.x = __float2bfloat16_rn(v0);
    t.y = __float2bfloat16_rn(v1);
    uint32_t u; memcpy(&u, &t, 4); return u;
}
__device__ __forceinline__ void split_pair(float v0, float v1, uint32_t& hi, uint32_t& lo) {
    __nv_bfloat16 h0 = __float2bfloat16_rn(v0), h1 = __float2bfloat16_rn(v1);
    float r0 = v0 - __bfloat162float(h0), r1 = v1 - __bfloat162float(h1);
    __nv_bfloat162 th; th.x = h0; th.y = h1;
    __nv_bfloat162 tl; tl.x = __float2bfloat16_rn(r0); tl.y = __float2bfloat16_rn(r1);
    memcpy(&hi, &th, 4); memcpy(&lo, &tl, 4);
}

// ---------------- scratch (device globals) -----------------------------------
__device__ float g_x[ROWS * D];
__device__ float g_h[ROWS * D];
__device__ __nv_bfloat16 g_qkv_hi[ROWS * 3 * D];
__device__ __nv_bfloat16 g_qkv_lo[ROWS * 3 * D];
__device__ __nv_bfloat16 g_ln_hi[ROWS * D];
__device__ __nv_bfloat16 g_ln_lo[ROWS * D];
__device__ __nv_bfloat16 g_mid_hi[ROWS * MSZ];
__device__ __nv_bfloat16 g_mid_lo[ROWS * MSZ];
__device__ __nv_bfloat16 g_wqkv_hi[LNUM * 3 * D * D];
__device__ __nv_bfloat16 g_wqkv_lo[LNUM * 3 * D * D];
__device__ __nv_bfloat16 g_w1_hi[LNUM * MSZ * D];
__device__ __nv_bfloat16 g_w1_lo[LNUM * MSZ * D];
__device__ __nv_bfloat16 g_w2_hi[LNUM * D * MSZ];
__device__ __nv_bfloat16 g_w2_lo[LNUM * D * MSZ];
__device__ __nv_bfloat16 g_wun_hi[V * D];
__device__ __nv_bfloat16 g_wun_lo[V * D];

// ---------------- weight split fp32 -> bf16 hi/lo ----------------------------
__global__ __launch_bounds__(256) void cvt_kernel(
    const float* __restrict__ w, __nv_bfloat16* __restrict__ hi,
    __nv_bfloat16* __restrict__ lo, int n)
{
    int i = blockIdx.x * 256 + threadIdx.x;
    if (i < n) {
        float v = w[i];
        __nv_bfloat16 h = __float2bfloat16_rn(v);
        hi[i] = h;
        lo[i] = __float2bfloat16_rn(v - __bfloat162float(h));
    }
}

// ---------------- embedding --------------------------------------------------
__global__ __launch_bounds__(256) void embed_kernel(
    const float* __restrict__ toks, const float* __restrict__ Wtok,
    const float* __restrict__ Wpos, float* __restrict__ x)
{
    int bt = blockIdx.x;
    int t = bt % TT;
    __shared__ float tk[V];
    if (threadIdx.x < V) tk[threadIdx.x] = toks[(size_t)bt * V + threadIdx.x];
    __syncthreads();
    for (int d = threadIdx.x; d < D; d += 256) {
        float s = Wpos[(size_t)d * TMAX + t];
        const float* wr = Wtok + (size_t)d * V;
        #pragma unroll 16
        for (int v = 0; v < V; v++) s += tk[v] * wr[v];
        x[(size_t)bt * D + d] = s;
    }
}

// ---------------- layernorm -> bf16 hi/lo outputs ----------------------------
__global__ __launch_bounds__(256) void ln_kernel(
    const float* __restrict__ x, const float* __restrict__ g,
    const float* __restrict__ be, __nv_bfloat16* __restrict__ ohi,
    __nv_bfloat16* __restrict__ olo)
{
    int row = blockIdx.x;
    const float* xr = x + (size_t)row * D;
    int tid = threadIdx.x;
    float v[4];
    float s = 0.f;
    #pragma unroll
    for (int i = 0; i < 4; i++) { v[i] = xr[tid + i * 256]; s += v[i]; }

    __shared__ float red[8];
    #pragma unroll
    for (int o = 16; o; o >>= 1) s += __shfl_xor_sync(0xffffffffu, s, o);
    if ((tid & 31) == 0) red[tid >> 5] = s;
    __syncthreads();
    if (tid < 32) {
        float t2 = (tid < 8) ? red[tid] : 0.f;
        #pragma unroll
        for (int o = 4; o; o >>= 1) t2 += __shfl_xor_sync(0xffffffffu, t2, o);
        if (tid == 0) red[0] = t2;
    }
    __syncthreads();
    float mean = red[0] * (1.f / D);
    __syncthreads();

    float s2 = 0.f;
    #pragma unroll
    for (int i = 0; i < 4; i++) { float d0 = v[i] - mean; s2 += d0 * d0; }
    #pragma unroll
    for (int o = 16; o; o >>= 1) s2 += __shfl_xor_sync(0xffffffffu, s2, o);
    if ((tid & 31) == 0) red[tid >> 5] = s2;
    __syncthreads();
    if (tid < 32) {
        float t2 = (tid < 8) ? red[tid] : 0.f;
        #pragma unroll
        for (int o = 4; o; o >>= 1) t2 += __shfl_xor_sync(0xffffffffu, t2, o);
        if (tid == 0) red[0] = t2;
    }
    __syncthreads();
    float var = red[0] * (1.f / D);
    float rstd = rsqrtf(var + EPS);

    size_t base = (size_t)row * D;
    #pragma unroll
    for (int i = 0; i < 4; i++) {
        int d0 = tid + i * 256;
        float vv = (v[i] - mean) * rstd * g[d0] + be[d0];
        __nv_bfloat16 hh = __float2bfloat16_rn(vv);
        ohi[base + d0] = hh;
        olo[base + d0] = __float2bfloat16_rn(vv - __bfloat162float(hh));
    }
}

// ---------------- split-bf16 NT GEMM via mma.sync ----------------------------
#define GT 256
#define TILE 128
#define BKC 32
#define PITCHB 80
#define ABYTES (128 * PITCHB)
#define BUFBYTES (4 * ABYTES)
#define SMEM_TOT (2 * BUFBYTES)

// mode 0: C = acc (+bias) (opt relu), fp32
// mode 1: v = relu?(acc + bias); write bf16 split to Ohi/Olo
// mode 2: C = acc + bias + add1 + addh, fp32 (C may alias add1)
__global__ __launch_bounds__(GT) void gemm_mma(
    const __nv_bfloat16* __restrict__ Ahi, const __nv_bfloat16* __restrict__ Alo,
    const __nv_bfloat16* __restrict__ Bhi, const __nv_bfloat16* __restrict__ Blo,
    const float* __restrict__ bias, float* __restrict__ C,
    const float* __restrict__ add1, const float* __restrict__ addh,
    __nv_bfloat16* __restrict__ Ohi, __nv_bfloat16* __restrict__ Olo,
    int N, int K, int relu, int mode)
{
    extern __shared__ char sm[];
    uint32_t sb = smem_to_u32(sm);
    int tid = threadIdx.x;
    int wid = tid >> 5, lane = tid & 31;
    int wm = wid & 1, wn = wid >> 1;
    int rowA0 = blockIdx.y * TILE;
    int colB0 = blockIdx.x * TILE;

    float acc[4][4][4];
    #pragma unroll
    for (int i = 0; i < 4; i++)
        #pragma unroll
        for (int j = 0; j < 4; j++)
            #pragma unroll
            for (int k = 0; k < 4; k++) acc[i][j][k] = 0.f;

    int l_r0 = tid >> 2;
    int l_r1 = (256 + tid) >> 2;
    int l_c0 = (tid & 3) * 8;

    const int nch = K / BKC;

    auto issue = [&](int c, int b) {
        int k0 = c * BKC;
        uint32_t base = sb + b * BUFBYTES;
        #pragma unroll
        for (int i = 0; i < 2; i++) {
            int r = i ? l_r1 : l_r0;
            uint32_t doff = (uint32_t)(r * PITCHB + l_c0 * 2);
            size_t ga = (size_t)(rowA0 + r) * K + k0 + l_c0;
            int br = colB0 + r; if (br > N - 1) br = N - 1;
            size_t gb = (size_t)br * K + k0 + l_c0;
            CP_ASYNC16(base + 0 * ABYTES + doff, Ahi + ga);
            CP_ASYNC16(base + 1 * ABYTES + doff, Alo + ga);
            CP_ASYNC16(base + 2 * ABYTES + doff, Bhi + gb);
            CP_ASYNC16(base + 3 * ABYTES + doff, Blo + gb);
        }
        CP_COMMIT();
    };

    issue(0, 0);

    uint32_t a_off = (uint32_t)((wm * 64 + (lane & 15)) * PITCHB + (lane >> 4) * 16);
    uint32_t b_off = (uint32_t)((wn * 32 + (lane & 7)) * PITCHB + ((lane >> 3) & 1) * 16);

    for (int c = 0; c < nch; c++) {
        int b = c & 1;
        if (c + 1 < nch) { issue(c + 1, b ^ 1); CP_WAIT(1); }
        else             { CP_WAIT(0); }
        __syncthreads();

        uint32_t sAH = sb + b * BUFBYTES + 0 * ABYTES;
        uint32_t sAL = sb + b * BUFBYTES + 1 * ABYTES;
        uint32_t sBH = sb + b * BUFBYTES + 2 * ABYTES;
        uint32_t sBL = sb + b * BUFBYTES + 3 * ABYTES;

        #pragma unroll
        for (int kk = 0; kk < 2; kk++) {
            uint32_t ah[4][4], al[4][4], bh[4][2], bl[4][2];
            #pragma unroll
            for (int mt = 0; mt < 4; mt++) {
                uint32_t ao = a_off + mt * 16 * PITCHB + kk * 32;
                ldsm_x4(ah[mt][0], ah[mt][1], ah[mt][2], ah[mt][3], sAH + ao);
                ldsm_x4(al[mt][0], al[mt][1], al[mt][2], al[mt][3], sAL + ao);
            }
            #pragma unroll
            for (int nt = 0; nt < 4; nt++) {
                uint32_t bo = b_off + nt * 8 * PITCHB + kk * 32;
                ldsm_x2(bh[nt][0], bh[nt][1], sBH + bo);
                ldsm_x2(bl[nt][0], bl[nt][1], sBL + bo);
            }
            #pragma unroll
            for (int mt = 0; mt < 4; mt++)
                #pragma unroll
                for (int nt = 0; nt < 4; nt++) {
                    mma_bf16(acc[mt][nt], ah[mt], bh[nt]);
                    mma_bf16(acc[mt][nt], ah[mt], bl[nt]);
                    mma_bf16(acc[mt][nt], al[mt], bh[nt]);
                }
        }
        __syncthreads();
    }

    int r_base = rowA0 + wm * 64 + (lane >> 2);
    int c_base = colB0 + wn * 32 + (lane & 3) * 2;
    #pragma unroll
    for (int mt = 0; mt < 4; mt++) {
        #pragma unroll
        for (int half = 0; half < 2; half++) {
            int row = r_base + mt * 16 + half * 8;
            #pragma unroll
            for (int nt = 0; nt < 4; nt++) {
                int col = c_base + nt * 8;
                if (col < N) {
                    float v0 = acc[mt][nt][half * 2 + 0];
                    float v1 = acc[mt][nt][half * 2 + 1];
                    if (bias) { v0 += bias[col]; if (col + 1 < N) v1 += bias[col + 1]; }
                    if (relu) { v0 = fmaxf(v0, 0.f); v1 = fmaxf(v1, 0.f); }
                    size_t i0 = (size_t)row * N + col;
                    if (mode == 2) {
                        v0 += add1[i0] + addh[i0];
                        if (col + 1 < N) v1 += add1[i0 + 1] + addh[i0 + 1];
                    }
                    if (mode == 1) {
                        __nv_bfloat16 h0 = __float2bfloat16_rn(v0);
                        Ohi[i0] = h0;
                        Olo[i0] = __float2bfloat16_rn(v0 - __bfloat162float(h0));
                        if (col + 1 < N) {
                            __nv_bfloat16 h1 = __float2bfloat16_rn(v1);
                            Ohi[i0 + 1] = h1;
                            Olo[i0 + 1] = __float2bfloat16_rn(v1 - __bfloat162float(h1));
                        }
                    } else {
                        C[i0] = v0;
                        if (col + 1 < N) C[i0 + 1] = v1;
                    }
                }
            }
        }
    }
}

// ---------------- tensor-core flash attention --------------------------------
// Per block: 128 query rows (8 warps x 16), one head, one batch.
// K/V tiles of 64 keys, double-buffered cp.async. Split-bf16 3-product MMAs.
#define PAT 144                     // smem pitch bytes for 64 bf16
#define TB (64 * PAT)               // 9216 per tensor tile
#define KVBUF (4 * TB)              // 36864: Kh Kl Vh Vl
#define ATT_SMEM (2 * KVBUF)        // 73728

__global__ __launch_bounds__(256) void attn_mma(
    const __nv_bfloat16* __restrict__ qhi, const __nv_bfloat16* __restrict__ qlo,
    const float* __restrict__ xres, float* __restrict__ out)
{
    extern __shared__ char sm[];
    uint32_t sb = smem_to_u32(sm);
    int tid = threadIdx.x;
    int w = tid >> 5, lane = tid & 31;
    int qb = blockIdx.x;
    int h = blockIdx.y, bz = blockIdx.z;
    int qt0 = qb * 128;

    const size_t rstr = 3 * D;                    // qkv row stride (elements)
    const size_t rowbase = (size_t)bz * TT;

    // ---- stage Q (hi/lo) into smem, then ldmatrix into registers ----
    {
        #pragma unroll
        for (int i = 0; i < 8; i++) {
            int lin = tid + i * 256;              // 0..2047
            int tens = lin >> 10;                 // 0 = hi, 1 = lo
            int r = (lin >> 3) & 127;
            int cg = lin & 7;
            const __nv_bfloat16* src = (tens ? qlo : qhi) +
                (rowbase + qt0 + r) * rstr + h * 192 + cg * 8;
            CP_ASYNC16(sb + tens * 18432 + r * PAT + cg * 16, src);
        }
        CP_COMMIT(); CP_WAIT(0);
        __syncthreads();
    }

    uint32_t qh[4][4], ql[4][4];
    {
        uint32_t qoff = (uint32_t)((w * 16 + (lane & 15)) * PAT + (lane >> 4) * 16);
        #pragma unroll
        for (int kc = 0; kc < 4; kc++) {
            ldsm_x4(qh[kc][0], qh[kc][1], qh[kc][2], qh[kc][3], sb + qoff + kc * 32);
            ldsm_x4(ql[kc][0], ql[kc][1], ql[kc][2], ql[kc][3], sb + 18432 + qoff + kc * 32);
        }
    }
    __syncthreads();   // smem now reusable for KV buffers

    // ---- softmax / output state ----
    float oacc[8][4];
    #pragma unroll
    for (int i = 0; i < 8; i++)
        #pragma unroll
        for (int j = 0; j < 4; j++) oacc[i][j] = 0.f;
    float mrow[2] = { -1e30f, -1e30f };
    float lrow[2] = { 0.f, 0.f };

    int r0 = lane >> 2;
    int t0 = qt0 + w * 16 + r0;
    int t1 = t0 + 8;

    const int ntiles = (qt0 + 128) / 64;

    auto issue_kv = [&](int s0, int buf) {
        #pragma unroll
        for (int i = 0; i < 8; i++) {
            int lin = tid + i * 256;              // 0..2047
            int tens = lin >> 9;                  // 0..3 : Kh Kl Vh Vl
            int r = (lin >> 3) & 63;
            int cg = lin & 7;
            const __nv_bfloat16* srcb = (tens & 1) ? qlo : qhi;
            int dimoff = (tens < 2) ? 64 : 128;
            const __nv_bfloat16* src = srcb +
                (rowbase + s0 + r) * rstr + h * 192 + dimoff + cg * 8;
            CP_ASYNC16(sb + buf * KVBUF + tens * TB + r * PAT + cg * 16, src);
        }
        CP_COMMIT();
    };

    issue_kv(0, 0);

    uint32_t kfoff = (uint32_t)((lane & 7) * PAT + ((lane >> 3) & 1) * 16);
    uint32_t vfoff = (uint32_t)((lane & 15) * PAT);

    for (int ti = 0; ti < ntiles; ti++) {
        int s0 = ti * 64;
        int buf = ti & 1;
        if (ti + 1 < ntiles) { issue_kv(s0 + 64, buf ^ 1); CP_WAIT(1); }
        else                 { CP_WAIT(0); }
        __syncthreads();

        uint32_t sKH = sb + buf * KVBUF + 0 * TB;
        uint32_t sKL = sb + buf * KVBUF + 1 * TB;
        uint32_t sVH = sb + buf * KVBUF + 2 * TB;
        uint32_t sVL = sb + buf * KVBUF + 3 * TB;

        // ---- S = Q K^T (3-product split) ----
        float sacc[8][4];
        #pragma unroll
        for (int i = 0; i < 8; i++)
            #pragma unroll
            for (int j = 0; j < 4; j++) sacc[i][j] = 0.f;

        #pragma unroll
        for (int kc = 0; kc < 4; kc++) {
            #pragma unroll
            for (int nt = 0; nt < 8; nt++) {
                uint32_t kh[2], kl[2];
                uint32_t ko = kfoff + nt * 8 * PAT + kc * 32;
                ldsm_x2(kh[0], kh[1], sKH + ko);
                ldsm_x2(kl[0], kl[1], sKL + ko);
                mma_bf16(sacc[nt], qh[kc], kh);
                mma_bf16(sacc[nt], qh[kc], kl);
                mma_bf16(sacc[nt], ql[kc], kh);
            }
        }

        // ---- scale + causal mask ----
        bool need_mask = (s0 + 64 > qt0 + w * 16);
        #pragma unroll
        for (int nt = 0; nt < 8; nt++) {
            #pragma unroll
            for (int i = 0; i < 4; i++) {
                float s = sacc[nt][i] * 0.125f;
                if (need_mask) {
                    int kidx = s0 + nt * 8 + 2 * (lane & 3) + (i & 1);
                    int trow = (i < 2) ? t0 : t1;
                    if (kidx > trow) s = -1e30f;
                }
                sacc[nt][i] = s;
            }
        }

        // ---- row max over tile ----
        float mt0 = -1e30f, mt1 = -1e30f;
        #pragma unroll
        for (int nt = 0; nt < 8; nt++) {
            mt0 = fmaxf(mt0, fmaxf(sacc[nt][0], sacc[nt][1]));
            mt1 = fmaxf(mt1, fmaxf(sacc[nt][2], sacc[nt][3]));
        }
        #pragma unroll
        for (int o = 1; o <= 2; o <<= 1) {
            mt0 = fmaxf(mt0, __shfl_xor_sync(0xffffffffu, mt0, o));
            mt1 = fmaxf(mt1, __shfl_xor_sync(0xffffffffu, mt1, o));
        }
        float mn0 = fmaxf(mrow[0], mt0);
        float mn1 = fmaxf(mrow[1], mt1);
        float sc0 = __expf(mrow[0] - mn0);
        float sc1 = __expf(mrow[1] - mn1);

        // ---- p = exp(s - m), row sums ----
        float rs0 = 0.f, rs1 = 0.f;
        #pragma unroll
        for (int nt = 0; nt < 8; nt++) {
            float p0 = __expf(sacc[nt][0] - mn0);
            float p1 = __expf(sacc[nt][1] - mn0);
            float p2 = __expf(sacc[nt][2] - mn1);
            float p3 = __expf(sacc[nt][3] - mn1);
            sacc[nt][0] = p0; sacc[nt][1] = p1; sacc[nt][2] = p2; sacc[nt][3] = p3;
            rs0 += p0 + p1; rs1 += p2 + p3;
        }
        #pragma unroll
        for (int o = 1; o <= 2; o <<= 1) {
            rs0 += __shfl_xor_sync(0xffffffffu, rs0, o);
            rs1 += __shfl_xor_sync(0xffffffffu, rs1, o);
        }
        lrow[0] = lrow[0] * sc0 + rs0;
        lrow[1] = lrow[1] * sc1 + rs1;
        mrow[0] = mn0; mrow[1] = mn1;

        // ---- rescale O ----
        #pragma unroll
        for (int nt2 = 0; nt2 < 8; nt2++) {
            oacc[nt2][0] *= sc0; oacc[nt2][1] *= sc0;
            oacc[nt2][2] *= sc1; oacc[nt2][3] *= sc1;
        }

        // ---- O += P V (3-product split, V via ldmatrix.trans) ----
        #pragma unroll
        for (int kc2 = 0; kc2 < 4; kc2++) {
            uint32_t ah[4], al[4];
            split_pair(sacc[2*kc2][0],   sacc[2*kc2][1],   ah[0], al[0]);
            split_pair(sacc[2*kc2][2],   sacc[2*kc2][3],   ah[1], al[1]);
            split_pair(sacc[2*kc2+1][0], sacc[2*kc2+1][1], ah[2], al[2]);
            split_pair(sacc[2*kc2+1][2], sacc[2*kc2+1][3], ah[3], al[3]);
            #pragma unroll
            for (int nt2 = 0; nt2 < 8; nt2++) {
                uint32_t vh[2], vl[2];
                uint32_t vo = vfoff + kc2 * 16 * PAT + nt2 * 16;
                ldsm_x2t(vh[0], vh[1], sVH + vo);
                ldsm_x2t(vl[0], vl[1], sVL + vo);
                mma_bf16(oacc[nt2], ah, vh);
                mma_bf16(oacc[nt2], al, vh);
                mma_bf16(oacc[nt2], ah, vl);
            }
        }
        __syncthreads();
    }

    // ---- epilogue: h = x + O/l ----
    float inv0 = 1.f / lrow[0];
    float inv1 = 1.f / lrow[1];
    #pragma unroll
    for (int nt2 = 0; nt2 < 8; nt2++) {
        int dim = h * 64 + nt2 * 8 + 2 * (lane & 3);
        size_t i0 = (rowbase + t0) * D + dim;
        size_t i1 = (rowbase + t1) * D + dim;
        out[i0]     = xres[i0]     + oacc[nt2][0] * inv0;
        out[i0 + 1] = xres[i0 + 1] + oacc[nt2][1] * inv0;
        out[i1]     = xres[i1]     + oacc[nt2][2] * inv1;
        out[i1 + 1] = xres[i1 + 1] + oacc[nt2][3] * inv1;
    }
}

// ---------------- driver -----------------------------------------------------
extern "C" void kernel_launch(void* const* d_in, const int* in_sizes, int n_in,
                              void* d_out, int out_size)
{
    const float* toks  = (const float*)d_in[0];
    const float* W_tok = (const float*)d_in[1];
    const float* W_pos = (const float*)d_in[2];
    const float* Wqkv  = (const float*)d_in[3];
    const float* g1    = (const float*)d_in[4];
    const float* be1   = (const float*)d_in[5];
    const float* W1    = (const float*)d_in[6];
    const float* bm1   = (const float*)d_in[7];
    const float* W2    = (const float*)d_in[8];
    const float* bm2   = (const float*)d_in[9];
    const float* g2    = (const float*)d_in[10];
    const float* be2   = (const float*)d_in[11];
    const float* gf    = (const float*)d_in[12];
    const float* bf    = (const float*)d_in[13];
    const float* Wun   = (const float*)d_in[14];
    const float* bun   = (const float*)d_in[15];
    float* out = (float*)d_out;

    float *px, *ph;
    __nv_bfloat16 *pqh, *pql, *plnh, *plnl, *pmidh, *pmidl;
    __nv_bfloat16 *pwqh, *pwql, *pw1h, *pw1l, *pw2h, *pw2l, *pwuh, *pwul;
    cudaGetSymbolAddress((void**)&px,    g_x);
    cudaGetSymbolAddress((void**)&ph,    g_h);
    cudaGetSymbolAddress((void**)&pqh,   g_qkv_hi);
    cudaGetSymbolAddress((void**)&pql,   g_qkv_lo);
    cudaGetSymbolAddress((void**)&plnh,  g_ln_hi);
    cudaGetSymbolAddress((void**)&plnl,  g_ln_lo);
    cudaGetSymbolAddress((void**)&pmidh, g_mid_hi);
    cudaGetSymbolAddress((void**)&pmidl, g_mid_lo);
    cudaGetSymbolAddress((void**)&pwqh,  g_wqkv_hi);
    cudaGetSymbolAddress((void**)&pwql,  g_wqkv_lo);
    cudaGetSymbolAddress((void**)&pw1h,  g_w1_hi);
    cudaGetSymbolAddress((void**)&pw1l,  g_w1_lo);
    cudaGetSymbolAddress((void**)&pw2h,  g_w2_hi);
    cudaGetSymbolAddress((void**)&pw2l,  g_w2_lo);
    cudaGetSymbolAddress((void**)&pwuh,  g_wun_hi);
    cudaGetSymbolAddress((void**)&pwul,  g_wun_lo);

    cudaFuncSetAttribute(gemm_mma, cudaFuncAttributeMaxDynamicSharedMemorySize, SMEM_TOT);
    cudaFuncSetAttribute(attn_mma, cudaFuncAttributeMaxDynamicSharedMemorySize, ATT_SMEM);

    // split weights to bf16 hi/lo
    {
        int n;
        n = LNUM * 3 * D * D; cvt_kernel<<<(n + 255) / 256, 256>>>(Wqkv, pwqh, pwql, n);
        n = LNUM * MSZ * D;   cvt_kernel<<<(n + 255) / 256, 256>>>(W1, pw1h, pw1l, n);
        n = LNUM * D * MSZ;   cvt_kernel<<<(n + 255) / 256, 256>>>(W2, pw2h, pw2l, n);
        n = V * D;            cvt_kernel<<<(n + 255) / 256, 256>>>(Wun, pwuh, pwul, n);
    }

    // embedding
    embed_kernel<<<ROWS, 256>>>(toks, W_tok, W_pos, px);

    for (int l = 0; l < LNUM; l++) {
        __nv_bfloat16* wqh = pwqh + (size_t)l * 3 * D * D;
        __nv_bfloat16* wql = pwql + (size_t)l * 3 * D * D;
        __nv_bfloat16* w1h = pw1h + (size_t)l * MSZ * D;
        __nv_bfloat16* w1l = pw1l + (size_t)l * MSZ * D;
        __nv_bfloat16* w2h = pw2h + (size_t)l * D * MSZ;
        __nv_bfloat16* w2l = pw2l + (size_t)l * D * MSZ;

        // ln1 -> qkv gemm (bf16 split out) -> attention (fused h = x + attn)
        ln_kernel<<<ROWS, 256>>>(px, g1 + l * D, be1 + l * D, plnh, plnl);
        {
            dim3 grid(3 * D / TILE, ROWS / TILE);
            gemm_mma<<<grid, GT, SMEM_TOT>>>(plnh, plnl, wqh, wql, nullptr, nullptr,
                                             nullptr, nullptr, pqh, pql,
                                             3 * D, D, 0, 1);
        }
        {
            dim3 grid(TT / 128, H, BB);
            attn_mma<<<grid, 256, ATT_SMEM>>>(pqh, pql, px, ph);
        }

        // ln2 -> mlp1 (relu, bf16 split out) -> mlp2 (fused x = x + h + mlp)
        ln_kernel<<<ROWS, 256>>>(ph, g2 + l * D, be2 + l * D, plnh, plnl);
        {
            dim3 grid(MSZ / TILE, ROWS / TILE);
            gemm_mma<<<grid, GT, SMEM_TOT>>>(plnh, plnl, w1h, w1l,
                                             bm1 + (size_t)l * MSZ, nullptr,
                                             nullptr, nullptr, pmidh, pmidl,
                                             MSZ, D, 1, 1);
        }
        {
            dim3 grid(D / TILE, ROWS / TILE);
            gemm_mma<<<grid, GT, SMEM_TOT>>>(pmidh, pmidl, w2h, w2l,
                                             bm2 + (size_t)l * D, px,
                                             px, ph, nullptr, nullptr,
                                             D, MSZ, 0, 2);
        }
    }

    // final layernorm + unembed (N=64)
    ln_kernel<<<ROWS, 256>>>(px, gf, bf, plnh, plnl);
    {
        dim3 grid(1, ROWS / TILE);
        gemm_mma<<<grid, GT, SMEM_TOT>>>(plnh, plnl, pwuh, pwul, bun, out,
                                         nullptr, nullptr, nullptr, nullptr,
                                         V, D, 0, 0);
    }
}